// round 3
// baseline (speedup 1.0000x reference)
#include <cuda_runtime.h>
#include <cuda_bf16.h>
#include <math.h>

// ---------------- Problem constants ----------------
#define BATCH 32
#define DEPTH 12
#define DIM 768
#define HEADS 12
#define HEAD_DIM 64
#define HIDDEN 3072
#define NP 196
#define NTOK 197
#define NUM_CLASSES 1000
#define M_ROWS (BATCH * NTOK)          // 6304
#define SCALE_QK 0.125f                // 64^-0.5

// ---------------- Device scratch (no allocation allowed) ----------------
__device__ float g_h[M_ROWS * DIM];            // residual stream
__device__ float g_a[M_ROWS * DIM];            // ln output / attn-o buffer
__device__ float g_qkv[M_ROWS * 3 * DIM];      // qkv
__device__ float g_S[BATCH * HEADS * NTOK * NTOK]; // attention scores
__device__ float g_hid[M_ROWS * HIDDEN];       // mlp hidden
__device__ float g_p[BATCH * NP * DIM];        // patches
__device__ float g_cls[BATCH * DIM];           // final cls ln

// ---------------- Patch gather ----------------
__global__ void patch_gather(const float* __restrict__ x, float* __restrict__ p) {
    int idx = blockIdx.x * blockDim.x + threadIdx.x;
    int total = BATCH * NP * DIM;
    if (idx >= total) return;
    int c  = idx % DIM;
    int np = (idx / DIM) % NP;
    int b  = idx / (DIM * NP);
    int ch = c / 256;
    int py = (c / 16) % 16;
    int px = c % 16;
    int gy = np / 14, gx = np % 14;
    p[idx] = x[((size_t)(b * 3 + ch) * 224 + gy * 16 + py) * 224 + gx * 16 + px];
}

// ---------------- Assemble h = concat(cls, patches) + pos ----------------
__global__ void assemble_h(const float* __restrict__ tmp, const float* __restrict__ cls_tok,
                           const float* __restrict__ pos, float* __restrict__ h) {
    int idx = blockIdx.x * blockDim.x + threadIdx.x;
    int total = M_ROWS * DIM;
    if (idx >= total) return;
    int d = idx % DIM;
    int n = (idx / DIM) % NTOK;
    int b = idx / (DIM * NTOK);
    float v = (n == 0) ? cls_tok[d] : tmp[((size_t)b * NP + (n - 1)) * DIM + d];
    h[idx] = v + pos[(size_t)n * DIM + d];
}

// ---------------- LayerNorm (one block per row) ----------------
__global__ void ln_kernel(const float* __restrict__ x, size_t rowStride,
                          const float* __restrict__ w, const float* __restrict__ b,
                          float* __restrict__ y) {
    int row = blockIdx.x;
    const float* xr = x + (size_t)row * rowStride;
    float s = 0.f, sq = 0.f;
    for (int d = threadIdx.x; d < DIM; d += blockDim.x) {
        float v = xr[d]; s += v; sq += v * v;
    }
    __shared__ float rs[8], rq[8];
    int lane = threadIdx.x & 31, warp = threadIdx.x >> 5;
    for (int o = 16; o; o >>= 1) { s += __shfl_xor_sync(~0u, s, o); sq += __shfl_xor_sync(~0u, sq, o); }
    if (lane == 0) { rs[warp] = s; rq[warp] = sq; }
    __syncthreads();
    if (warp == 0) {
        s  = (lane < 8) ? rs[lane] : 0.f;
        sq = (lane < 8) ? rq[lane] : 0.f;
        for (int o = 4; o; o >>= 1) { s += __shfl_xor_sync(~0u, s, o); sq += __shfl_xor_sync(~0u, sq, o); }
        if (lane == 0) { rs[0] = s; rq[0] = sq; }
    }
    __syncthreads();
    float mean = rs[0] / DIM;
    float var  = rq[0] / DIM - mean * mean;
    var = fmaxf(var, 0.f);
    float inv = rsqrtf(var + 1e-6f);
    float* yr = y + (size_t)row * DIM;
    for (int d = threadIdx.x; d < DIM; d += blockDim.x)
        yr[d] = (xr[d] - mean) * inv * w[d] + b[d];
}

// ---------------- 128x128x8 SGEMM, 8x8 per thread, fused epilogues ----------------
// C[M,N] = A[M,K] @ B[K,N] + bias ; mode: 0=bias, 1=bias+residual(R), 2=bias+gelu
// Requirements used here: N % 128 == 0, K % 8 == 0 (true for all call sites).
#define TBM 128
#define TBN 128
#define TBK 8
__global__ __launch_bounds__(256) void gemm_kernel(
    const float* __restrict__ A, const float* __restrict__ B,
    const float* __restrict__ bias, const float* __restrict__ R,
    float* __restrict__ C, int M, int N, int K, int mode) {
    __shared__ float As[TBK][TBM];   // transposed A tile
    __shared__ float Bs[TBK][TBN];

    int tid = threadIdx.x;
    int tx = tid & 15;        // 0..15 -> N
    int ty = tid >> 4;        // 0..15 -> M
    int mbase = blockIdx.y * TBM;
    int nbase = blockIdx.x * TBN;

    // A-load coords: one float4 per thread (128 rows x 8 cols)
    int a_row = tid >> 1;              // 0..127
    int a_col = (tid & 1) << 2;        // 0 or 4
    // B-load coords: one float4 per thread (8 rows x 128 cols)
    int b_row = tid >> 5;              // 0..7
    int b_col = (tid & 31) << 2;       // 0..124

    float acc[8][8];
    #pragma unroll
    for (int i = 0; i < 8; i++)
        #pragma unroll
        for (int j = 0; j < 8; j++) acc[i][j] = 0.f;

    int gm_a = mbase + a_row;
    const float* Aptr = A + (size_t)gm_a * K + a_col;
    const float* Bptr = B + (size_t)b_row * N + nbase + b_col;

    for (int k0 = 0; k0 < K; k0 += TBK) {
        float4 av;
        if (gm_a < M) av = *(const float4*)(Aptr + k0);
        else av = make_float4(0.f, 0.f, 0.f, 0.f);
        float4 bv = *(const float4*)(Bptr + (size_t)k0 * N);

        As[a_col + 0][a_row] = av.x;
        As[a_col + 1][a_row] = av.y;
        As[a_col + 2][a_row] = av.z;
        As[a_col + 3][a_row] = av.w;
        *(float4*)&Bs[b_row][b_col] = bv;
        __syncthreads();

        #pragma unroll
        for (int kk = 0; kk < TBK; kk++) {
            float ar[8], br[8];
            #pragma unroll
            for (int i = 0; i < 8; i++) ar[i] = As[kk][ty * 8 + i];
            #pragma unroll
            for (int j = 0; j < 8; j++) br[j] = Bs[kk][tx * 8 + j];
            #pragma unroll
            for (int i = 0; i < 8; i++)
                #pragma unroll
                for (int j = 0; j < 8; j++) acc[i][j] += ar[i] * br[j];
        }
        __syncthreads();
    }

    // Epilogue
    int ncol0 = nbase + tx * 8;
    float bi[8];
    #pragma unroll
    for (int j = 0; j < 8; j++) bi[j] = bias[ncol0 + j];

    #pragma unroll
    for (int i = 0; i < 8; i++) {
        int gm = mbase + ty * 8 + i;
        if (gm >= M) continue;
        float* crow = C + (size_t)gm * N + ncol0;
        if (mode == 0) {
            #pragma unroll
            for (int j = 0; j < 8; j++) crow[j] = acc[i][j] + bi[j];
        } else if (mode == 1) {
            const float* rrow = R + (size_t)gm * N + ncol0;
            #pragma unroll
            for (int j = 0; j < 8; j++) crow[j] = acc[i][j] + bi[j] + rrow[j];
        } else {
            #pragma unroll
            for (int j = 0; j < 8; j++) {
                float v = acc[i][j] + bi[j];
                crow[j] = 0.5f * v * (1.f + erff(v * 0.70710678118654752f));
            }
        }
    }
}

// ---------------- QK^T (batched per (b,h)) ----------------
__global__ __launch_bounds__(256) void qk_kernel(const float* __restrict__ qkv, float* __restrict__ S) {
    int bh = blockIdx.y;
    int b = bh / HEADS, hh = bh % HEADS;
    int n0 = blockIdx.x * 32;
    __shared__ float qs[32][65], ks[32][65];
    const float* qbase = qkv + (size_t)b * NTOK * (3 * DIM) + hh * HEAD_DIM;
    const float* kbase = qbase + DIM;
    #pragma unroll
    for (int i = 0; i < 8; i++) {
        int lin = threadIdx.x + 256 * i;
        int r = lin >> 6, d = lin & 63;
        int n = n0 + r;
        qs[r][d] = (n < NTOK) ? qbase[(size_t)n * (3 * DIM) + d] : 0.f;
    }
    float* Sbase = S + (size_t)bh * NTOK * NTOK;
    for (int m0 = 0; m0 < NTOK; m0 += 32) {
        #pragma unroll
        for (int i = 0; i < 8; i++) {
            int lin = threadIdx.x + 256 * i;
            int r = lin >> 6, d = lin & 63;
            int m = m0 + r;
            ks[r][d] = (m < NTOK) ? kbase[(size_t)m * (3 * DIM) + d] : 0.f;
        }
        __syncthreads();
        #pragma unroll
        for (int i = 0; i < 4; i++) {
            int lin = threadIdx.x + 256 * i;
            int n = lin >> 5, m = lin & 31;
            float accv = 0.f;
            #pragma unroll
            for (int d = 0; d < 64; d++) accv += qs[n][d] * ks[m][d];
            int gn = n0 + n, gm = m0 + m;
            if (gn < NTOK && gm < NTOK)
                Sbase[(size_t)gn * NTOK + gm] = accv * SCALE_QK;
        }
        __syncthreads();
    }
}

// ---------------- Fused head-mix(pre) -> softmax -> head-mix(post) ----------------
__global__ __launch_bounds__(256) void mix_softmax_kernel(float* __restrict__ S,
                                                          const float* __restrict__ prew,
                                                          const float* __restrict__ postw) {
    int bn = blockIdx.x;
    int b = bn / NTOK, n = bn % NTOK;
    __shared__ float raw[HEADS][200];
    __shared__ float sm[HEADS][200];
    __shared__ float pw[HEADS * HEADS], qw[HEADS * HEADS];
    int tid = threadIdx.x;
    if (tid < HEADS * HEADS) { pw[tid] = prew[tid]; qw[tid] = postw[tid]; }
    float* Sb = S + (size_t)b * HEADS * NTOK * NTOK + (size_t)n * NTOK;
    for (int idx = tid; idx < HEADS * NTOK; idx += 256) {
        int h = idx / NTOK, m = idx % NTOK;
        raw[h][m] = Sb[(size_t)h * NTOK * NTOK + m];
    }
    __syncthreads();
    for (int idx = tid; idx < HEADS * NTOK; idx += 256) {
        int g = idx / NTOK, m = idx % NTOK;
        float accv = 0.f;
        #pragma unroll
        for (int h = 0; h < HEADS; h++) accv += raw[h][m] * pw[h * HEADS + g];
        sm[g][m] = accv;
    }
    __syncthreads();
    int warp = tid >> 5, lane = tid & 31;
    for (int g = warp; g < HEADS; g += 8) {
        float mx = -1e30f;
        for (int m = lane; m < NTOK; m += 32) mx = fmaxf(mx, sm[g][m]);
        for (int o = 16; o; o >>= 1) mx = fmaxf(mx, __shfl_xor_sync(~0u, mx, o));
        float sum = 0.f;
        for (int m = lane; m < NTOK; m += 32) { float e = __expf(sm[g][m] - mx); sm[g][m] = e; sum += e; }
        for (int o = 16; o; o >>= 1) sum += __shfl_xor_sync(~0u, sum, o);
        float inv = 1.f / sum;
        for (int m = lane; m < NTOK; m += 32) sm[g][m] *= inv;
    }
    __syncthreads();
    for (int idx = tid; idx < HEADS * NTOK; idx += 256) {
        int g = idx / NTOK, m = idx % NTOK;
        float accv = 0.f;
        #pragma unroll
        for (int h = 0; h < HEADS; h++) accv += sm[h][m] * qw[h * HEADS + g];
        Sb[(size_t)g * NTOK * NTOK + m] = accv;
    }
}

// ---------------- A @ V (batched per (b,h)), writes o in [B,N,DIM] layout ----------------
__global__ __launch_bounds__(256) void av_kernel(const float* __restrict__ qkv,
                                                 const float* __restrict__ S,
                                                 float* __restrict__ o) {
    int bh = blockIdx.y;
    int b = bh / HEADS, hh = bh % HEADS;
    int n0 = blockIdx.x * 32;
    __shared__ float as_[32][33], vs[32][65];
    const float* vbase = qkv + (size_t)b * NTOK * (3 * DIM) + 2 * DIM + hh * HEAD_DIM;
    const float* Sbase = S + (size_t)bh * NTOK * NTOK;
    float accv[8];
    #pragma unroll
    for (int i = 0; i < 8; i++) accv[i] = 0.f;
    for (int m0 = 0; m0 < NTOK; m0 += 32) {
        #pragma unroll
        for (int i = 0; i < 4; i++) {
            int lin = threadIdx.x + 256 * i;
            int n = lin >> 5, mm = lin & 31;
            as_[n][mm] = (n0 + n < NTOK && m0 + mm < NTOK)
                       ? Sbase[(size_t)(n0 + n) * NTOK + m0 + mm] : 0.f;
        }
        #pragma unroll
        for (int i = 0; i < 8; i++) {
            int lin = threadIdx.x + 256 * i;
            int mm = lin >> 6, d = lin & 63;
            vs[mm][d] = (m0 + mm < NTOK) ? vbase[(size_t)(m0 + mm) * (3 * DIM) + d] : 0.f;
        }
        __syncthreads();
        #pragma unroll
        for (int i = 0; i < 8; i++) {
            int lin = threadIdx.x + 256 * i;
            int n = lin >> 6, d = lin & 63;
            #pragma unroll
            for (int mm = 0; mm < 32; mm++) accv[i] += as_[n][mm] * vs[mm][d];
        }
        __syncthreads();
    }
    #pragma unroll
    for (int i = 0; i < 8; i++) {
        int lin = threadIdx.x + 256 * i;
        int n = lin >> 6, d = lin & 63;
        if (n0 + n < NTOK)
            o[((size_t)b * NTOK + n0 + n) * DIM + hh * HEAD_DIM + d] = accv[i];
    }
}

// ---------------- Classifier head ----------------
__global__ void head_kernel(const float* __restrict__ cls, const float* __restrict__ W,
                            const float* __restrict__ bias, float* __restrict__ out) {
    int b = blockIdx.x;
    __shared__ float c[DIM];
    for (int d = threadIdx.x; d < DIM; d += blockDim.x) c[d] = cls[(size_t)b * DIM + d];
    __syncthreads();
    for (int cc = threadIdx.x; cc < NUM_CLASSES; cc += blockDim.x) {
        float accv = bias[cc];
        for (int d = 0; d < DIM; d++) accv += c[d] * W[(size_t)d * NUM_CLASSES + cc];
        out[(size_t)b * NUM_CLASSES + cc] = accv;
    }
}

// ---------------- Launcher ----------------
static inline void run_gemm(const float* A, const float* B, const float* bias,
                            const float* R, float* C, int M, int N, int K, int mode) {
    dim3 grid(N / TBN, (M + TBM - 1) / TBM);
    gemm_kernel<<<grid, 256>>>(A, B, bias, R, C, M, N, K, mode);
}

extern "C" void kernel_launch(void* const* d_in, const int* in_sizes, int n_in,
                              void* d_out, int out_size) {
    const float* x          = (const float*)d_in[0];
    const float* patch_w    = (const float*)d_in[1];
    const float* patch_b    = (const float*)d_in[2];
    const float* cls_token  = (const float*)d_in[3];
    const float* pos_embed  = (const float*)d_in[4];
    const float* ln1_w      = (const float*)d_in[5];
    const float* ln1_b      = (const float*)d_in[6];
    const float* qkv_w      = (const float*)d_in[7];
    const float* qkv_b      = (const float*)d_in[8];
    const float* pre_w      = (const float*)d_in[9];
    const float* post_w     = (const float*)d_in[10];
    const float* attnproj_w = (const float*)d_in[11];
    const float* attnproj_b = (const float*)d_in[12];
    const float* ln2_w      = (const float*)d_in[13];
    const float* ln2_b      = (const float*)d_in[14];
    const float* fc1_w      = (const float*)d_in[15];
    const float* fc1_b      = (const float*)d_in[16];
    const float* fc2_w      = (const float*)d_in[17];
    const float* fc2_b      = (const float*)d_in[18];
    const float* norm_w     = (const float*)d_in[19];
    const float* norm_b     = (const float*)d_in[20];
    const float* head_w     = (const float*)d_in[21];
    const float* head_b     = (const float*)d_in[22];

    float *h, *a, *qkv, *S, *hid, *p, *cls;
    cudaGetSymbolAddress((void**)&h,   g_h);
    cudaGetSymbolAddress((void**)&a,   g_a);
    cudaGetSymbolAddress((void**)&qkv, g_qkv);
    cudaGetSymbolAddress((void**)&S,   g_S);
    cudaGetSymbolAddress((void**)&hid, g_hid);
    cudaGetSymbolAddress((void**)&p,   g_p);
    cudaGetSymbolAddress((void**)&cls, g_cls);

    // Patch embed
    {
        int total = BATCH * NP * DIM;
        patch_gather<<<(total + 255) / 256, 256>>>(x, p);
    }
    run_gemm(p, patch_w, patch_b, nullptr, hid /*tmp*/, BATCH * NP, DIM, DIM, 0);
    {
        int total = M_ROWS * DIM;
        assemble_h<<<(total + 255) / 256, 256>>>(hid, cls_token, pos_embed, h);
    }

    dim3 attn_grid((NTOK + 31) / 32, BATCH * HEADS);

    for (int i = 0; i < DEPTH; i++) {
        ln_kernel<<<M_ROWS, 256>>>(h, DIM, ln1_w + (size_t)i * DIM, ln1_b + (size_t)i * DIM, a);
        run_gemm(a, qkv_w + (size_t)i * DIM * 3 * DIM, qkv_b + (size_t)i * 3 * DIM,
                 nullptr, qkv, M_ROWS, 3 * DIM, DIM, 0);
        qk_kernel<<<attn_grid, 256>>>(qkv, S);
        mix_softmax_kernel<<<M_ROWS, 256>>>(S, pre_w + (size_t)i * HEADS * HEADS,
                                            post_w + (size_t)i * HEADS * HEADS);
        av_kernel<<<attn_grid, 256>>>(qkv, S, a);
        run_gemm(a, attnproj_w + (size_t)i * DIM * DIM, attnproj_b + (size_t)i * DIM,
                 h, h, M_ROWS, DIM, DIM, 1);
        ln_kernel<<<M_ROWS, 256>>>(h, DIM, ln2_w + (size_t)i * DIM, ln2_b + (size_t)i * DIM, a);
        run_gemm(a, fc1_w + (size_t)i * DIM * HIDDEN, fc1_b + (size_t)i * HIDDEN,
                 nullptr, hid, M_ROWS, HIDDEN, DIM, 2);
        run_gemm(hid, fc2_w + (size_t)i * HIDDEN * DIM, fc2_b + (size_t)i * DIM,
                 h, h, M_ROWS, DIM, HIDDEN, 1);
    }

    ln_kernel<<<BATCH, 256>>>(h, (size_t)NTOK * DIM, norm_w, norm_b, cls);
    head_kernel<<<BATCH, 256>>>(cls, head_w, head_b, (float*)d_out);
}

// round 4
// speedup vs baseline: 1.3011x; 1.3011x over previous
#include <cuda_runtime.h>
#include <cuda_bf16.h>
#include <math.h>

// ---------------- Problem constants ----------------
#define BATCH 32
#define DEPTH 12
#define DIM 768
#define HEADS 12
#define HEAD_DIM 64
#define HIDDEN 3072
#define NP 196
#define NTOK 197
#define NUM_CLASSES 1000
#define M_ROWS (BATCH * NTOK)          // 6304
#define SCALE_QK 0.125f                // 64^-0.5

// ---------------- Device scratch (no allocation allowed) ----------------
__device__ float g_h[M_ROWS * DIM];            // residual stream
__device__ float g_a[M_ROWS * DIM];            // ln output / attn-o buffer
__device__ float g_qkv[M_ROWS * 3 * DIM];      // qkv
__device__ float g_S[BATCH * HEADS * NTOK * NTOK]; // attention scores
__device__ float g_hid[M_ROWS * HIDDEN];       // mlp hidden
__device__ float g_p[BATCH * NP * DIM];        // patches
__device__ float g_cls[BATCH * DIM];           // final cls ln

// ---------------- f32x2 packed helpers ----------------
__device__ __forceinline__ unsigned long long pack_dup(float x) {
    unsigned long long r;
    asm("mov.b64 %0, {%1, %2};" : "=l"(r) : "f"(x), "f"(x));
    return r;
}
__device__ __forceinline__ void ffma2(unsigned long long& c, unsigned long long a, unsigned long long b) {
    asm("fma.rn.f32x2 %0, %1, %2, %0;" : "+l"(c) : "l"(a), "l"(b));
}
__device__ __forceinline__ void unpack2(unsigned long long u, float& lo, float& hi) {
    asm("mov.b64 {%0, %1}, %2;" : "=f"(lo), "=f"(hi) : "l"(u));
}

// ---------------- Patch gather ----------------
__global__ void patch_gather(const float* __restrict__ x, float* __restrict__ p) {
    int idx = blockIdx.x * blockDim.x + threadIdx.x;
    int total = BATCH * NP * DIM;
    if (idx >= total) return;
    int c  = idx % DIM;
    int np = (idx / DIM) % NP;
    int b  = idx / (DIM * NP);
    int ch = c / 256;
    int py = (c / 16) % 16;
    int px = c % 16;
    int gy = np / 14, gx = np % 14;
    p[idx] = x[((size_t)(b * 3 + ch) * 224 + gy * 16 + py) * 224 + gx * 16 + px];
}

// ---------------- Assemble h = concat(cls, patches) + pos ----------------
__global__ void assemble_h(const float* __restrict__ tmp, const float* __restrict__ cls_tok,
                           const float* __restrict__ pos, float* __restrict__ h) {
    int idx = blockIdx.x * blockDim.x + threadIdx.x;
    int total = M_ROWS * DIM;
    if (idx >= total) return;
    int d = idx % DIM;
    int n = (idx / DIM) % NTOK;
    int b = idx / (DIM * NTOK);
    float v = (n == 0) ? cls_tok[d] : tmp[((size_t)b * NP + (n - 1)) * DIM + d];
    h[idx] = v + pos[(size_t)n * DIM + d];
}

// ---------------- LayerNorm (one block per row) ----------------
__global__ void ln_kernel(const float* __restrict__ x, size_t rowStride,
                          const float* __restrict__ w, const float* __restrict__ b,
                          float* __restrict__ y) {
    int row = blockIdx.x;
    const float* xr = x + (size_t)row * rowStride;
    float s = 0.f, sq = 0.f;
    for (int d = threadIdx.x; d < DIM; d += blockDim.x) {
        float v = xr[d]; s += v; sq += v * v;
    }
    __shared__ float rs[8], rq[8];
    int lane = threadIdx.x & 31, warp = threadIdx.x >> 5;
    for (int o = 16; o; o >>= 1) { s += __shfl_xor_sync(~0u, s, o); sq += __shfl_xor_sync(~0u, sq, o); }
    if (lane == 0) { rs[warp] = s; rq[warp] = sq; }
    __syncthreads();
    if (warp == 0) {
        s  = (lane < 8) ? rs[lane] : 0.f;
        sq = (lane < 8) ? rq[lane] : 0.f;
        for (int o = 4; o; o >>= 1) { s += __shfl_xor_sync(~0u, s, o); sq += __shfl_xor_sync(~0u, sq, o); }
        if (lane == 0) { rs[0] = s; rq[0] = sq; }
    }
    __syncthreads();
    float mean = rs[0] / DIM;
    float var  = rq[0] / DIM - mean * mean;
    var = fmaxf(var, 0.f);
    float inv = rsqrtf(var + 1e-6f);
    float* yr = y + (size_t)row * DIM;
    for (int d = threadIdx.x; d < DIM; d += blockDim.x)
        yr[d] = (xr[d] - mean) * inv * w[d] + b[d];
}

// ---------------- 128x128x16 SGEMM with packed fma.rn.f32x2 ----------------
// C[M,N] = A[M,K] @ B[K,N] + bias ; mode: 0=bias, 1=bias+residual(R), 2=bias+gelu
// Requires N % 128 == 0, K % 16 == 0 (true for all call sites).
#define TBM 128
#define TBN 128
#define TBK 16
__global__ __launch_bounds__(256) void gemm_kernel(
    const float* __restrict__ A, const float* __restrict__ B,
    const float* __restrict__ bias, const float* __restrict__ R,
    float* __restrict__ C, int M, int N, int K, int mode) {
    __shared__ float As[TBK][TBM];   // transposed A tile
    __shared__ float Bs[TBK][TBN];

    int tid = threadIdx.x;
    int tx = tid & 15;        // 0..15 -> N fragment
    int ty = tid >> 4;        // 0..15 -> M fragment
    int mbase = blockIdx.y * TBM;
    int nbase = blockIdx.x * TBN;

    // A-load coords: 128 rows x 16 cols, 2 float4 per thread
    int a_row = tid >> 1;               // 0..127
    int a_col = (tid & 1) << 3;         // 0 or 8
    // B-load coords: 16 rows x 128 cols, 2 float4 per thread
    int b_row = tid >> 4;               // 0..15
    int b_col = (tid & 15) << 3;        // 0..120

    // acc[i][jp]: i = 8 output rows (ty*4+0..3, 64+ty*4+0..3),
    // jp = 4 packed col-pairs (cols tx*4+{0,1},{2,3}, 64+tx*4+{0,1},{2,3})
    unsigned long long acc[8][4];
    #pragma unroll
    for (int i = 0; i < 8; i++)
        #pragma unroll
        for (int j = 0; j < 4; j++) acc[i][j] = 0ull;

    int gm_a = mbase + a_row;
    const float* Aptr = A + (size_t)gm_a * K + a_col;
    const float* Bptr = B + (size_t)b_row * N + nbase + b_col;

    // Prologue: load tile 0
    float4 av0, av1, bv0, bv1;
    if (gm_a < M) { av0 = *(const float4*)(Aptr);  av1 = *(const float4*)(Aptr + 4); }
    else { av0 = make_float4(0,0,0,0); av1 = av0; }
    bv0 = *(const float4*)(Bptr);
    bv1 = *(const float4*)(Bptr + 4);

    {
        As[a_col + 0][a_row] = av0.x; As[a_col + 1][a_row] = av0.y;
        As[a_col + 2][a_row] = av0.z; As[a_col + 3][a_row] = av0.w;
        As[a_col + 4][a_row] = av1.x; As[a_col + 5][a_row] = av1.y;
        As[a_col + 6][a_row] = av1.z; As[a_col + 7][a_row] = av1.w;
        *(float4*)&Bs[b_row][b_col]     = bv0;
        *(float4*)&Bs[b_row][b_col + 4] = bv1;
    }
    __syncthreads();

    for (int k0 = 0; k0 < K; k0 += TBK) {
        bool has_next = (k0 + TBK) < K;
        if (has_next) {
            const float* Ap = Aptr + (k0 + TBK);
            if (gm_a < M) { av0 = *(const float4*)(Ap); av1 = *(const float4*)(Ap + 4); }
            else { av0 = make_float4(0,0,0,0); av1 = av0; }
            const float* Bp = Bptr + (size_t)(k0 + TBK) * N;
            bv0 = *(const float4*)(Bp);
            bv1 = *(const float4*)(Bp + 4);
        }

        #pragma unroll
        for (int kk = 0; kk < TBK; kk++) {
            float4 a0 = *(const float4*)&As[kk][ty * 4];
            float4 a1 = *(const float4*)&As[kk][64 + ty * 4];
            float4 b0 = *(const float4*)&Bs[kk][tx * 4];
            float4 b1 = *(const float4*)&Bs[kk][64 + tx * 4];
            unsigned long long B2[4];
            B2[0] = *(unsigned long long*)&b0.x;   // (b0.x, b0.y)
            B2[1] = *(unsigned long long*)&b0.z;   // (b0.z, b0.w)
            B2[2] = *(unsigned long long*)&b1.x;
            B2[3] = *(unsigned long long*)&b1.z;
            float ar[8] = {a0.x, a0.y, a0.z, a0.w, a1.x, a1.y, a1.z, a1.w};
            #pragma unroll
            for (int i = 0; i < 8; i++) {
                unsigned long long A2 = pack_dup(ar[i]);
                ffma2(acc[i][0], A2, B2[0]);
                ffma2(acc[i][1], A2, B2[1]);
                ffma2(acc[i][2], A2, B2[2]);
                ffma2(acc[i][3], A2, B2[3]);
            }
        }
        __syncthreads();
        if (has_next) {
            As[a_col + 0][a_row] = av0.x; As[a_col + 1][a_row] = av0.y;
            As[a_col + 2][a_row] = av0.z; As[a_col + 3][a_row] = av0.w;
            As[a_col + 4][a_row] = av1.x; As[a_col + 5][a_row] = av1.y;
            As[a_col + 6][a_row] = av1.z; As[a_col + 7][a_row] = av1.w;
            *(float4*)&Bs[b_row][b_col]     = bv0;
            *(float4*)&Bs[b_row][b_col + 4] = bv1;
            __syncthreads();
        }
    }

    // Epilogue
    int c0 = nbase + tx * 4;
    float4 bi0 = *(const float4*)&bias[c0];
    float4 bi1 = *(const float4*)&bias[c0 + 64];
    float bi[8] = {bi0.x, bi0.y, bi0.z, bi0.w, bi1.x, bi1.y, bi1.z, bi1.w};

    #pragma unroll
    for (int i = 0; i < 8; i++) {
        int gm = mbase + ((i < 4) ? (ty * 4 + i) : (64 + ty * 4 + (i - 4)));
        if (gm >= M) continue;
        float o[8];
        unpack2(acc[i][0], o[0], o[1]);
        unpack2(acc[i][1], o[2], o[3]);
        unpack2(acc[i][2], o[4], o[5]);
        unpack2(acc[i][3], o[6], o[7]);
        #pragma unroll
        for (int j = 0; j < 8; j++) o[j] += bi[j];
        if (mode == 2) {
            #pragma unroll
            for (int j = 0; j < 8; j++)
                o[j] = 0.5f * o[j] * (1.f + erff(o[j] * 0.70710678118654752f));
        } else if (mode == 1) {
            const float* rrow = R + (size_t)gm * N + c0;
            float4 r0 = *(const float4*)(rrow);
            float4 r1 = *(const float4*)(rrow + 64);
            o[0] += r0.x; o[1] += r0.y; o[2] += r0.z; o[3] += r0.w;
            o[4] += r1.x; o[5] += r1.y; o[6] += r1.z; o[7] += r1.w;
        }
        float* crow = C + (size_t)gm * N + c0;
        *(float4*)(crow)      = make_float4(o[0], o[1], o[2], o[3]);
        *(float4*)(crow + 64) = make_float4(o[4], o[5], o[6], o[7]);
    }
}

// ---------------- QK^T (batched per (b,h)) ----------------
__global__ __launch_bounds__(256) void qk_kernel(const float* __restrict__ qkv, float* __restrict__ S) {
    int bh = blockIdx.y;
    int b = bh / HEADS, hh = bh % HEADS;
    int n0 = blockIdx.x * 32;
    __shared__ float qs[32][65], ks[32][65];
    const float* qbase = qkv + (size_t)b * NTOK * (3 * DIM) + hh * HEAD_DIM;
    const float* kbase = qbase + DIM;
    #pragma unroll
    for (int i = 0; i < 8; i++) {
        int lin = threadIdx.x + 256 * i;
        int r = lin >> 6, d = lin & 63;
        int n = n0 + r;
        qs[r][d] = (n < NTOK) ? qbase[(size_t)n * (3 * DIM) + d] : 0.f;
    }
    float* Sbase = S + (size_t)bh * NTOK * NTOK;
    for (int m0 = 0; m0 < NTOK; m0 += 32) {
        #pragma unroll
        for (int i = 0; i < 8; i++) {
            int lin = threadIdx.x + 256 * i;
            int r = lin >> 6, d = lin & 63;
            int m = m0 + r;
            ks[r][d] = (m < NTOK) ? kbase[(size_t)m * (3 * DIM) + d] : 0.f;
        }
        __syncthreads();
        #pragma unroll
        for (int i = 0; i < 4; i++) {
            int lin = threadIdx.x + 256 * i;
            int n = lin >> 5, m = lin & 31;
            float accv = 0.f;
            #pragma unroll
            for (int d = 0; d < 64; d++) accv += qs[n][d] * ks[m][d];
            int gn = n0 + n, gm = m0 + m;
            if (gn < NTOK && gm < NTOK)
                Sbase[(size_t)gn * NTOK + gm] = accv * SCALE_QK;
        }
        __syncthreads();
    }
}

// ---------------- Fused head-mix(pre) -> softmax -> head-mix(post) ----------------
__global__ __launch_bounds__(256) void mix_softmax_kernel(float* __restrict__ S,
                                                          const float* __restrict__ prew,
                                                          const float* __restrict__ postw) {
    int bn = blockIdx.x;
    int b = bn / NTOK, n = bn % NTOK;
    __shared__ float raw[HEADS][200];
    __shared__ float sm[HEADS][200];
    __shared__ float pw[HEADS * HEADS], qw[HEADS * HEADS];
    int tid = threadIdx.x;
    if (tid < HEADS * HEADS) { pw[tid] = prew[tid]; qw[tid] = postw[tid]; }
    float* Sb = S + (size_t)b * HEADS * NTOK * NTOK + (size_t)n * NTOK;
    for (int idx = tid; idx < HEADS * NTOK; idx += 256) {
        int h = idx / NTOK, m = idx % NTOK;
        raw[h][m] = Sb[(size_t)h * NTOK * NTOK + m];
    }
    __syncthreads();
    for (int idx = tid; idx < HEADS * NTOK; idx += 256) {
        int g = idx / NTOK, m = idx % NTOK;
        float accv = 0.f;
        #pragma unroll
        for (int h = 0; h < HEADS; h++) accv += raw[h][m] * pw[h * HEADS + g];
        sm[g][m] = accv;
    }
    __syncthreads();
    int warp = tid >> 5, lane = tid & 31;
    for (int g = warp; g < HEADS; g += 8) {
        float mx = -1e30f;
        for (int m = lane; m < NTOK; m += 32) mx = fmaxf(mx, sm[g][m]);
        for (int o = 16; o; o >>= 1) mx = fmaxf(mx, __shfl_xor_sync(~0u, mx, o));
        float sum = 0.f;
        for (int m = lane; m < NTOK; m += 32) { float e = __expf(sm[g][m] - mx); sm[g][m] = e; sum += e; }
        for (int o = 16; o; o >>= 1) sum += __shfl_xor_sync(~0u, sum, o);
        float inv = 1.f / sum;
        for (int m = lane; m < NTOK; m += 32) sm[g][m] *= inv;
    }
    __syncthreads();
    for (int idx = tid; idx < HEADS * NTOK; idx += 256) {
        int g = idx / NTOK, m = idx % NTOK;
        float accv = 0.f;
        #pragma unroll
        for (int h = 0; h < HEADS; h++) accv += sm[h][m] * qw[h * HEADS + g];
        Sb[(size_t)g * NTOK * NTOK + m] = accv;
    }
}

// ---------------- A @ V (batched per (b,h)), writes o in [B,N,DIM] layout ----------------
__global__ __launch_bounds__(256) void av_kernel(const float* __restrict__ qkv,
                                                 const float* __restrict__ S,
                                                 float* __restrict__ o) {
    int bh = blockIdx.y;
    int b = bh / HEADS, hh = bh % HEADS;
    int n0 = blockIdx.x * 32;
    __shared__ float as_[32][33], vs[32][65];
    const float* vbase = qkv + (size_t)b * NTOK * (3 * DIM) + 2 * DIM + hh * HEAD_DIM;
    const float* Sbase = S + (size_t)bh * NTOK * NTOK;
    float accv[8];
    #pragma unroll
    for (int i = 0; i < 8; i++) accv[i] = 0.f;
    for (int m0 = 0; m0 < NTOK; m0 += 32) {
        #pragma unroll
        for (int i = 0; i < 4; i++) {
            int lin = threadIdx.x + 256 * i;
            int n = lin >> 5, mm = lin & 31;
            as_[n][mm] = (n0 + n < NTOK && m0 + mm < NTOK)
                       ? Sbase[(size_t)(n0 + n) * NTOK + m0 + mm] : 0.f;
        }
        #pragma unroll
        for (int i = 0; i < 8; i++) {
            int lin = threadIdx.x + 256 * i;
            int mm = lin >> 6, d = lin & 63;
            vs[mm][d] = (m0 + mm < NTOK) ? vbase[(size_t)(m0 + mm) * (3 * DIM) + d] : 0.f;
        }
        __syncthreads();
        #pragma unroll
        for (int i = 0; i < 8; i++) {
            int lin = threadIdx.x + 256 * i;
            int n = lin >> 6, d = lin & 63;
            #pragma unroll
            for (int mm = 0; mm < 32; mm++) accv[i] += as_[n][mm] * vs[mm][d];
        }
        __syncthreads();
    }
    #pragma unroll
    for (int i = 0; i < 8; i++) {
        int lin = threadIdx.x + 256 * i;
        int n = lin >> 6, d = lin & 63;
        if (n0 + n < NTOK)
            o[((size_t)b * NTOK + n0 + n) * DIM + hh * HEAD_DIM + d] = accv[i];
    }
}

// ---------------- Classifier head ----------------
__global__ void head_kernel(const float* __restrict__ cls, const float* __restrict__ W,
                            const float* __restrict__ bias, float* __restrict__ out) {
    int b = blockIdx.x;
    __shared__ float c[DIM];
    for (int d = threadIdx.x; d < DIM; d += blockDim.x) c[d] = cls[(size_t)b * DIM + d];
    __syncthreads();
    for (int cc = threadIdx.x; cc < NUM_CLASSES; cc += blockDim.x) {
        float accv = bias[cc];
        for (int d = 0; d < DIM; d++) accv += c[d] * W[(size_t)d * NUM_CLASSES + cc];
        out[(size_t)b * NUM_CLASSES + cc] = accv;
    }
}

// ---------------- Launcher ----------------
static inline void run_gemm(const float* A, const float* B, const float* bias,
                            const float* R, float* C, int M, int N, int K, int mode) {
    dim3 grid(N / TBN, (M + TBM - 1) / TBM);
    gemm_kernel<<<grid, 256>>>(A, B, bias, R, C, M, N, K, mode);
}

extern "C" void kernel_launch(void* const* d_in, const int* in_sizes, int n_in,
                              void* d_out, int out_size) {
    const float* x          = (const float*)d_in[0];
    const float* patch_w    = (const float*)d_in[1];
    const float* patch_b    = (const float*)d_in[2];
    const float* cls_token  = (const float*)d_in[3];
    const float* pos_embed  = (const float*)d_in[4];
    const float* ln1_w      = (const float*)d_in[5];
    const float* ln1_b      = (const float*)d_in[6];
    const float* qkv_w      = (const float*)d_in[7];
    const float* qkv_b      = (const float*)d_in[8];
    const float* pre_w      = (const float*)d_in[9];
    const float* post_w     = (const float*)d_in[10];
    const float* attnproj_w = (const float*)d_in[11];
    const float* attnproj_b = (const float*)d_in[12];
    const float* ln2_w      = (const float*)d_in[13];
    const float* ln2_b      = (const float*)d_in[14];
    const float* fc1_w      = (const float*)d_in[15];
    const float* fc1_b      = (const float*)d_in[16];
    const float* fc2_w      = (const float*)d_in[17];
    const float* fc2_b      = (const float*)d_in[18];
    const float* norm_w     = (const float*)d_in[19];
    const float* norm_b     = (const float*)d_in[20];
    const float* head_w     = (const float*)d_in[21];
    const float* head_b     = (const float*)d_in[22];

    float *h, *a, *qkv, *S, *hid, *p, *cls;
    cudaGetSymbolAddress((void**)&h,   g_h);
    cudaGetSymbolAddress((void**)&a,   g_a);
    cudaGetSymbolAddress((void**)&qkv, g_qkv);
    cudaGetSymbolAddress((void**)&S,   g_S);
    cudaGetSymbolAddress((void**)&hid, g_hid);
    cudaGetSymbolAddress((void**)&p,   g_p);
    cudaGetSymbolAddress((void**)&cls, g_cls);

    // Patch embed
    {
        int total = BATCH * NP * DIM;
        patch_gather<<<(total + 255) / 256, 256>>>(x, p);
    }
    run_gemm(p, patch_w, patch_b, nullptr, hid /*tmp*/, BATCH * NP, DIM, DIM, 0);
    {
        int total = M_ROWS * DIM;
        assemble_h<<<(total + 255) / 256, 256>>>(hid, cls_token, pos_embed, h);
    }

    dim3 attn_grid((NTOK + 31) / 32, BATCH * HEADS);

    for (int i = 0; i < DEPTH; i++) {
        ln_kernel<<<M_ROWS, 256>>>(h, DIM, ln1_w + (size_t)i * DIM, ln1_b + (size_t)i * DIM, a);
        run_gemm(a, qkv_w + (size_t)i * DIM * 3 * DIM, qkv_b + (size_t)i * 3 * DIM,
                 nullptr, qkv, M_ROWS, 3 * DIM, DIM, 0);
        qk_kernel<<<attn_grid, 256>>>(qkv, S);
        mix_softmax_kernel<<<M_ROWS, 256>>>(S, pre_w + (size_t)i * HEADS * HEADS,
                                            post_w + (size_t)i * HEADS * HEADS);
        av_kernel<<<attn_grid, 256>>>(qkv, S, a);
        run_gemm(a, attnproj_w + (size_t)i * DIM * DIM, attnproj_b + (size_t)i * DIM,
                 h, h, M_ROWS, DIM, DIM, 1);
        ln_kernel<<<M_ROWS, 256>>>(h, DIM, ln2_w + (size_t)i * DIM, ln2_b + (size_t)i * DIM, a);
        run_gemm(a, fc1_w + (size_t)i * DIM * HIDDEN, fc1_b + (size_t)i * HIDDEN,
                 nullptr, hid, M_ROWS, HIDDEN, DIM, 2);
        run_gemm(hid, fc2_w + (size_t)i * HIDDEN * DIM, fc2_b + (size_t)i * DIM,
                 h, h, M_ROWS, DIM, HIDDEN, 1);
    }

    ln_kernel<<<BATCH, 256>>>(h, (size_t)NTOK * DIM, norm_w, norm_b, cls);
    head_kernel<<<BATCH, 256>>>(cls, head_w, head_b, (float*)d_out);
}

// round 5
// speedup vs baseline: 2.1679x; 1.6662x over previous
#include <cuda_runtime.h>
#include <cuda_bf16.h>
#include <math.h>
#include <stdint.h>

// ---------------- Problem constants ----------------
#define BATCH 32
#define DEPTH 12
#define DIM 768
#define HEADS 12
#define HEAD_DIM 64
#define HIDDEN 3072
#define NP 196
#define NTOK 197
#define NUM_CLASSES 1000
#define M_ROWS (BATCH * NTOK)          // 6304
#define SCALE_QK 0.125f                // 64^-0.5

// ---------------- Device scratch (no allocation allowed) ----------------
__device__ float g_h[M_ROWS * DIM];            // residual stream
__device__ float g_a[M_ROWS * DIM];            // ln output / attn-o buffer
__device__ float g_qkv[M_ROWS * 3 * DIM];      // qkv
__device__ float g_S[BATCH * HEADS * NTOK * NTOK]; // attention scores
__device__ float g_hid[M_ROWS * HIDDEN];       // mlp hidden
__device__ float g_p[BATCH * NP * DIM];        // patches
__device__ float g_cls[BATCH * DIM];           // final cls ln

// ---------------- TF32 helpers ----------------
__device__ __forceinline__ float to_tf32(float x) {
    uint32_t r;
    asm("cvt.rna.tf32.f32 %0, %1;" : "=r"(r) : "f"(x));
    return __uint_as_float(r);
}
__device__ __forceinline__ void mma_tf32(float& c0, float& c1, float& c2, float& c3,
                                         uint32_t a0, uint32_t a1, uint32_t a2, uint32_t a3,
                                         uint32_t b0, uint32_t b1) {
    asm volatile("mma.sync.aligned.m16n8k8.row.col.f32.tf32.tf32.f32 "
                 "{%0,%1,%2,%3}, {%4,%5,%6,%7}, {%8,%9}, {%0,%1,%2,%3};"
                 : "+f"(c0), "+f"(c1), "+f"(c2), "+f"(c3)
                 : "r"(a0), "r"(a1), "r"(a2), "r"(a3), "r"(b0), "r"(b1));
}

// ---------------- Patch gather ----------------
__global__ void patch_gather(const float* __restrict__ x, float* __restrict__ p) {
    int idx = blockIdx.x * blockDim.x + threadIdx.x;
    int total = BATCH * NP * DIM;
    if (idx >= total) return;
    int c  = idx % DIM;
    int np = (idx / DIM) % NP;
    int b  = idx / (DIM * NP);
    int ch = c / 256;
    int py = (c / 16) % 16;
    int px = c % 16;
    int gy = np / 14, gx = np % 14;
    p[idx] = x[((size_t)(b * 3 + ch) * 224 + gy * 16 + py) * 224 + gx * 16 + px];
}

// ---------------- Assemble h = concat(cls, patches) + pos ----------------
__global__ void assemble_h(const float* __restrict__ tmp, const float* __restrict__ cls_tok,
                           const float* __restrict__ pos, float* __restrict__ h) {
    int idx = blockIdx.x * blockDim.x + threadIdx.x;
    int total = M_ROWS * DIM;
    if (idx >= total) return;
    int d = idx % DIM;
    int n = (idx / DIM) % NTOK;
    int b = idx / (DIM * NTOK);
    float v = (n == 0) ? cls_tok[d] : tmp[((size_t)b * NP + (n - 1)) * DIM + d];
    h[idx] = v + pos[(size_t)n * DIM + d];
}

// ---------------- LayerNorm (one block per row) ----------------
__global__ void ln_kernel(const float* __restrict__ x, size_t rowStride,
                          const float* __restrict__ w, const float* __restrict__ b,
                          float* __restrict__ y) {
    int row = blockIdx.x;
    const float* xr = x + (size_t)row * rowStride;
    float s = 0.f, sq = 0.f;
    for (int d = threadIdx.x; d < DIM; d += blockDim.x) {
        float v = xr[d]; s += v; sq += v * v;
    }
    __shared__ float rs[8], rq[8];
    int lane = threadIdx.x & 31, warp = threadIdx.x >> 5;
    for (int o = 16; o; o >>= 1) { s += __shfl_xor_sync(~0u, s, o); sq += __shfl_xor_sync(~0u, sq, o); }
    if (lane == 0) { rs[warp] = s; rq[warp] = sq; }
    __syncthreads();
    if (warp == 0) {
        s  = (lane < 8) ? rs[lane] : 0.f;
        sq = (lane < 8) ? rq[lane] : 0.f;
        for (int o = 4; o; o >>= 1) { s += __shfl_xor_sync(~0u, s, o); sq += __shfl_xor_sync(~0u, sq, o); }
        if (lane == 0) { rs[0] = s; rq[0] = sq; }
    }
    __syncthreads();
    float mean = rs[0] / DIM;
    float var  = rq[0] / DIM - mean * mean;
    var = fmaxf(var, 0.f);
    float inv = rsqrtf(var + 1e-6f);
    float* yr = y + (size_t)row * DIM;
    for (int d = threadIdx.x; d < DIM; d += blockDim.x)
        yr[d] = (xr[d] - mean) * inv * w[d] + b[d];
}

// ---------------- 128x128x16 TF32 tensor-core GEMM ----------------
// C[M,N] = A[M,K] @ B[K,N] + bias ; mode: 0=bias, 1=bias+residual(R), 2=bias+gelu
// Requires N % 128 == 0, K % 16 == 0 (true for all call sites).
#define TBM 128
#define TBN 128
#define TBK 16
#define APAD 8
#define LDT (TBM + APAD)   // 136 floats per SMEM row
__global__ __launch_bounds__(256) void gemm_kernel(
    const float* __restrict__ A, const float* __restrict__ B,
    const float* __restrict__ bias, const float* __restrict__ R,
    float* __restrict__ C, int M, int N, int K, int mode) {
    __shared__ float As[TBK][LDT];   // K-major A tile (transposed)
    __shared__ float Bs[TBK][LDT];

    int tid  = threadIdx.x;
    int wid  = tid >> 5;
    int lane = tid & 31;
    int lr = lane >> 2;        // 0..7
    int lc = lane & 3;         // 0..3

    // warp tile: 64 (M) x 32 (N); warps: 2 (M) x 4 (N)
    int wm = wid & 1;          // 0..1
    int wn = wid >> 1;         // 0..3
    int m0w = wm * 64;
    int n0w = wn * 32;

    int mbase = blockIdx.y * TBM;
    int nbase = blockIdx.x * TBN;

    // A-load coords: 128 rows x 16 cols, 2 float4 per thread
    int a_row = tid >> 1;               // 0..127
    int a_col = (tid & 1) << 3;         // 0 or 8
    // B-load coords: 16 rows x 128 cols, 2 float4 per thread
    int b_row = tid >> 4;               // 0..15
    int b_col = (tid & 15) << 3;        // 0..120

    float acc[4][4][4];                 // [m-tile][n-tile][frag]
    #pragma unroll
    for (int i = 0; i < 4; i++)
        #pragma unroll
        for (int j = 0; j < 4; j++)
            #pragma unroll
            for (int q = 0; q < 4; q++) acc[i][j][q] = 0.f;

    int gm_a = mbase + a_row;
    const float* Aptr = A + (size_t)gm_a * K + a_col;
    const float* Bptr = B + (size_t)b_row * N + nbase + b_col;

    float4 av0, av1, bv0, bv1;
    // Prologue: load tile 0
    if (gm_a < M) { av0 = *(const float4*)(Aptr);  av1 = *(const float4*)(Aptr + 4); }
    else { av0 = make_float4(0,0,0,0); av1 = av0; }
    bv0 = *(const float4*)(Bptr);
    bv1 = *(const float4*)(Bptr + 4);

    {
        As[a_col + 0][a_row] = to_tf32(av0.x); As[a_col + 1][a_row] = to_tf32(av0.y);
        As[a_col + 2][a_row] = to_tf32(av0.z); As[a_col + 3][a_row] = to_tf32(av0.w);
        As[a_col + 4][a_row] = to_tf32(av1.x); As[a_col + 5][a_row] = to_tf32(av1.y);
        As[a_col + 6][a_row] = to_tf32(av1.z); As[a_col + 7][a_row] = to_tf32(av1.w);
        float4 c0 = make_float4(to_tf32(bv0.x), to_tf32(bv0.y), to_tf32(bv0.z), to_tf32(bv0.w));
        float4 c1 = make_float4(to_tf32(bv1.x), to_tf32(bv1.y), to_tf32(bv1.z), to_tf32(bv1.w));
        *(float4*)&Bs[b_row][b_col]     = c0;
        *(float4*)&Bs[b_row][b_col + 4] = c1;
    }
    __syncthreads();

    for (int k0 = 0; k0 < K; k0 += TBK) {
        bool has_next = (k0 + TBK) < K;
        if (has_next) {
            const float* Ap = Aptr + (k0 + TBK);
            if (gm_a < M) { av0 = *(const float4*)(Ap); av1 = *(const float4*)(Ap + 4); }
            else { av0 = make_float4(0,0,0,0); av1 = av0; }
            const float* Bp = Bptr + (size_t)(k0 + TBK) * N;
            bv0 = *(const float4*)(Bp);
            bv1 = *(const float4*)(Bp + 4);
        }

        #pragma unroll
        for (int ks = 0; ks < 2; ks++) {
            int kk = ks * 8;
            uint32_t af[4][4], bf[4][2];
            #pragma unroll
            for (int mt = 0; mt < 4; mt++) {
                int mr = m0w + mt * 16 + lr;
                af[mt][0] = __float_as_uint(As[kk + lc][mr]);
                af[mt][1] = __float_as_uint(As[kk + lc][mr + 8]);
                af[mt][2] = __float_as_uint(As[kk + lc + 4][mr]);
                af[mt][3] = __float_as_uint(As[kk + lc + 4][mr + 8]);
            }
            #pragma unroll
            for (int nt = 0; nt < 4; nt++) {
                int nc = n0w + nt * 8 + lr;
                bf[nt][0] = __float_as_uint(Bs[kk + lc][nc]);
                bf[nt][1] = __float_as_uint(Bs[kk + lc + 4][nc]);
            }
            #pragma unroll
            for (int mt = 0; mt < 4; mt++)
                #pragma unroll
                for (int nt = 0; nt < 4; nt++)
                    mma_tf32(acc[mt][nt][0], acc[mt][nt][1], acc[mt][nt][2], acc[mt][nt][3],
                             af[mt][0], af[mt][1], af[mt][2], af[mt][3],
                             bf[nt][0], bf[nt][1]);
        }
        __syncthreads();
        if (has_next) {
            As[a_col + 0][a_row] = to_tf32(av0.x); As[a_col + 1][a_row] = to_tf32(av0.y);
            As[a_col + 2][a_row] = to_tf32(av0.z); As[a_col + 3][a_row] = to_tf32(av0.w);
            As[a_col + 4][a_row] = to_tf32(av1.x); As[a_col + 5][a_row] = to_tf32(av1.y);
            As[a_col + 6][a_row] = to_tf32(av1.z); As[a_col + 7][a_row] = to_tf32(av1.w);
            float4 c0 = make_float4(to_tf32(bv0.x), to_tf32(bv0.y), to_tf32(bv0.z), to_tf32(bv0.w));
            float4 c1 = make_float4(to_tf32(bv1.x), to_tf32(bv1.y), to_tf32(bv1.z), to_tf32(bv1.w));
            *(float4*)&Bs[b_row][b_col]     = c0;
            *(float4*)&Bs[b_row][b_col + 4] = c1;
            __syncthreads();
        }
    }

    // ---------------- Epilogue ----------------
    // Thread (in warp) owns, per (mt,nt): rows m0w+mt*16+lr (+8), cols n0w+nt*8+2*lc (+1)
    #pragma unroll
    for (int mt = 0; mt < 4; mt++) {
        #pragma unroll
        for (int half = 0; half < 2; half++) {
            int gm = mbase + m0w + mt * 16 + lr + half * 8;
            if (gm >= M) continue;
            #pragma unroll
            for (int nt = 0; nt < 4; nt++) {
                int gn = nbase + n0w + nt * 8 + 2 * lc;
                float v0 = acc[mt][nt][half * 2 + 0];
                float v1 = acc[mt][nt][half * 2 + 1];
                float2 bi = *(const float2*)&bias[gn];
                v0 += bi.x; v1 += bi.y;
                if (mode == 2) {
                    v0 = 0.5f * v0 * (1.f + erff(v0 * 0.70710678118654752f));
                    v1 = 0.5f * v1 * (1.f + erff(v1 * 0.70710678118654752f));
                } else if (mode == 1) {
                    float2 rr = *(const float2*)(R + (size_t)gm * N + gn);
                    v0 += rr.x; v1 += rr.y;
                }
                *(float2*)(C + (size_t)gm * N + gn) = make_float2(v0, v1);
            }
        }
    }
}

// ---------------- QK^T (batched per (b,h)) ----------------
__global__ __launch_bounds__(256) void qk_kernel(const float* __restrict__ qkv, float* __restrict__ S) {
    int bh = blockIdx.y;
    int b = bh / HEADS, hh = bh % HEADS;
    int n0 = blockIdx.x * 32;
    __shared__ float qs[32][65], ks[32][65];
    const float* qbase = qkv + (size_t)b * NTOK * (3 * DIM) + hh * HEAD_DIM;
    const float* kbase = qbase + DIM;
    #pragma unroll
    for (int i = 0; i < 8; i++) {
        int lin = threadIdx.x + 256 * i;
        int r = lin >> 6, d = lin & 63;
        int n = n0 + r;
        qs[r][d] = (n < NTOK) ? qbase[(size_t)n * (3 * DIM) + d] : 0.f;
    }
    float* Sbase = S + (size_t)bh * NTOK * NTOK;
    for (int m0 = 0; m0 < NTOK; m0 += 32) {
        #pragma unroll
        for (int i = 0; i < 8; i++) {
            int lin = threadIdx.x + 256 * i;
            int r = lin >> 6, d = lin & 63;
            int m = m0 + r;
            ks[r][d] = (m < NTOK) ? kbase[(size_t)m * (3 * DIM) + d] : 0.f;
        }
        __syncthreads();
        #pragma unroll
        for (int i = 0; i < 4; i++) {
            int lin = threadIdx.x + 256 * i;
            int n = lin >> 5, m = lin & 31;
            float accv = 0.f;
            #pragma unroll
            for (int d = 0; d < 64; d++) accv += qs[n][d] * ks[m][d];
            int gn = n0 + n, gm = m0 + m;
            if (gn < NTOK && gm < NTOK)
                Sbase[(size_t)gn * NTOK + gm] = accv * SCALE_QK;
        }
        __syncthreads();
    }
}

// ---------------- Fused head-mix(pre) -> softmax -> head-mix(post) ----------------
__global__ __launch_bounds__(256) void mix_softmax_kernel(float* __restrict__ S,
                                                          const float* __restrict__ prew,
                                                          const float* __restrict__ postw) {
    int bn = blockIdx.x;
    int b = bn / NTOK, n = bn % NTOK;
    __shared__ float raw[HEADS][200];
    __shared__ float sm[HEADS][200];
    __shared__ float pw[HEADS * HEADS], qw[HEADS * HEADS];
    int tid = threadIdx.x;
    if (tid < HEADS * HEADS) { pw[tid] = prew[tid]; qw[tid] = postw[tid]; }
    float* Sb = S + (size_t)b * HEADS * NTOK * NTOK + (size_t)n * NTOK;
    for (int idx = tid; idx < HEADS * NTOK; idx += 256) {
        int h = idx / NTOK, m = idx % NTOK;
        raw[h][m] = Sb[(size_t)h * NTOK * NTOK + m];
    }
    __syncthreads();
    for (int idx = tid; idx < HEADS * NTOK; idx += 256) {
        int g = idx / NTOK, m = idx % NTOK;
        float accv = 0.f;
        #pragma unroll
        for (int h = 0; h < HEADS; h++) accv += raw[h][m] * pw[h * HEADS + g];
        sm[g][m] = accv;
    }
    __syncthreads();
    int warp = tid >> 5, lane = tid & 31;
    for (int g = warp; g < HEADS; g += 8) {
        float mx = -1e30f;
        for (int m = lane; m < NTOK; m += 32) mx = fmaxf(mx, sm[g][m]);
        for (int o = 16; o; o >>= 1) mx = fmaxf(mx, __shfl_xor_sync(~0u, mx, o));
        float sum = 0.f;
        for (int m = lane; m < NTOK; m += 32) { float e = __expf(sm[g][m] - mx); sm[g][m] = e; sum += e; }
        for (int o = 16; o; o >>= 1) sum += __shfl_xor_sync(~0u, sum, o);
        float inv = 1.f / sum;
        for (int m = lane; m < NTOK; m += 32) sm[g][m] *= inv;
    }
    __syncthreads();
    for (int idx = tid; idx < HEADS * NTOK; idx += 256) {
        int g = idx / NTOK, m = idx % NTOK;
        float accv = 0.f;
        #pragma unroll
        for (int h = 0; h < HEADS; h++) accv += sm[h][m] * qw[h * HEADS + g];
        Sb[(size_t)g * NTOK * NTOK + m] = accv;
    }
}

// ---------------- A @ V (batched per (b,h)), writes o in [B,N,DIM] layout ----------------
__global__ __launch_bounds__(256) void av_kernel(const float* __restrict__ qkv,
                                                 const float* __restrict__ S,
                                                 float* __restrict__ o) {
    int bh = blockIdx.y;
    int b = bh / HEADS, hh = bh % HEADS;
    int n0 = blockIdx.x * 32;
    __shared__ float as_[32][33], vs[32][65];
    const float* vbase = qkv + (size_t)b * NTOK * (3 * DIM) + 2 * DIM + hh * HEAD_DIM;
    const float* Sbase = S + (size_t)bh * NTOK * NTOK;
    float accv[8];
    #pragma unroll
    for (int i = 0; i < 8; i++) accv[i] = 0.f;
    for (int m0 = 0; m0 < NTOK; m0 += 32) {
        #pragma unroll
        for (int i = 0; i < 4; i++) {
            int lin = threadIdx.x + 256 * i;
            int n = lin >> 5, mm = lin & 31;
            as_[n][mm] = (n0 + n < NTOK && m0 + mm < NTOK)
                       ? Sbase[(size_t)(n0 + n) * NTOK + m0 + mm] : 0.f;
        }
        #pragma unroll
        for (int i = 0; i < 8; i++) {
            int lin = threadIdx.x + 256 * i;
            int mm = lin >> 6, d = lin & 63;
            vs[mm][d] = (m0 + mm < NTOK) ? vbase[(size_t)(m0 + mm) * (3 * DIM) + d] : 0.f;
        }
        __syncthreads();
        #pragma unroll
        for (int i = 0; i < 8; i++) {
            int lin = threadIdx.x + 256 * i;
            int n = lin >> 6, d = lin & 63;
            #pragma unroll
            for (int mm = 0; mm < 32; mm++) accv[i] += as_[n][mm] * vs[mm][d];
        }
        __syncthreads();
    }
    #pragma unroll
    for (int i = 0; i < 8; i++) {
        int lin = threadIdx.x + 256 * i;
        int n = lin >> 6, d = lin & 63;
        if (n0 + n < NTOK)
            o[((size_t)b * NTOK + n0 + n) * DIM + hh * HEAD_DIM + d] = accv[i];
    }
}

// ---------------- Classifier head ----------------
__global__ void head_kernel(const float* __restrict__ cls, const float* __restrict__ W,
                            const float* __restrict__ bias, float* __restrict__ out) {
    int b = blockIdx.x;
    __shared__ float c[DIM];
    for (int d = threadIdx.x; d < DIM; d += blockDim.x) c[d] = cls[(size_t)b * DIM + d];
    __syncthreads();
    for (int cc = threadIdx.x; cc < NUM_CLASSES; cc += blockDim.x) {
        float accv = bias[cc];
        for (int d = 0; d < DIM; d++) accv += c[d] * W[(size_t)d * NUM_CLASSES + cc];
        out[(size_t)b * NUM_CLASSES + cc] = accv;
    }
}

// ---------------- Launcher ----------------
static inline void run_gemm(const float* A, const float* B, const float* bias,
                            const float* R, float* C, int M, int N, int K, int mode) {
    dim3 grid(N / TBN, (M + TBM - 1) / TBM);
    gemm_kernel<<<grid, 256>>>(A, B, bias, R, C, M, N, K, mode);
}

extern "C" void kernel_launch(void* const* d_in, const int* in_sizes, int n_in,
                              void* d_out, int out_size) {
    const float* x          = (const float*)d_in[0];
    const float* patch_w    = (const float*)d_in[1];
    const float* patch_b    = (const float*)d_in[2];
    const float* cls_token  = (const float*)d_in[3];
    const float* pos_embed  = (const float*)d_in[4];
    const float* ln1_w      = (const float*)d_in[5];
    const float* ln1_b      = (const float*)d_in[6];
    const float* qkv_w      = (const float*)d_in[7];
    const float* qkv_b      = (const float*)d_in[8];
    const float* pre_w      = (const float*)d_in[9];
    const float* post_w     = (const float*)d_in[10];
    const float* attnproj_w = (const float*)d_in[11];
    const float* attnproj_b = (const float*)d_in[12];
    const float* ln2_w      = (const float*)d_in[13];
    const float* ln2_b      = (const float*)d_in[14];
    const float* fc1_w      = (const float*)d_in[15];
    const float* fc1_b      = (const float*)d_in[16];
    const float* fc2_w      = (const float*)d_in[17];
    const float* fc2_b      = (const float*)d_in[18];
    const float* norm_w     = (const float*)d_in[19];
    const float* norm_b     = (const float*)d_in[20];
    const float* head_w     = (const float*)d_in[21];
    const float* head_b     = (const float*)d_in[22];

    float *h, *a, *qkv, *S, *hid, *p, *cls;
    cudaGetSymbolAddress((void**)&h,   g_h);
    cudaGetSymbolAddress((void**)&a,   g_a);
    cudaGetSymbolAddress((void**)&qkv, g_qkv);
    cudaGetSymbolAddress((void**)&S,   g_S);
    cudaGetSymbolAddress((void**)&hid, g_hid);
    cudaGetSymbolAddress((void**)&p,   g_p);
    cudaGetSymbolAddress((void**)&cls, g_cls);

    // Patch embed
    {
        int total = BATCH * NP * DIM;
        patch_gather<<<(total + 255) / 256, 256>>>(x, p);
    }
    run_gemm(p, patch_w, patch_b, nullptr, hid /*tmp*/, BATCH * NP, DIM, DIM, 0);
    {
        int total = M_ROWS * DIM;
        assemble_h<<<(total + 255) / 256, 256>>>(hid, cls_token, pos_embed, h);
    }

    dim3 attn_grid((NTOK + 31) / 32, BATCH * HEADS);

    for (int i = 0; i < DEPTH; i++) {
        ln_kernel<<<M_ROWS, 256>>>(h, DIM, ln1_w + (size_t)i * DIM, ln1_b + (size_t)i * DIM, a);
        run_gemm(a, qkv_w + (size_t)i * DIM * 3 * DIM, qkv_b + (size_t)i * 3 * DIM,
                 nullptr, qkv, M_ROWS, 3 * DIM, DIM, 0);
        qk_kernel<<<attn_grid, 256>>>(qkv, S);
        mix_softmax_kernel<<<M_ROWS, 256>>>(S, pre_w + (size_t)i * HEADS * HEADS,
                                            post_w + (size_t)i * HEADS * HEADS);
        av_kernel<<<attn_grid, 256>>>(qkv, S, a);
        run_gemm(a, attnproj_w + (size_t)i * DIM * DIM, attnproj_b + (size_t)i * DIM,
                 h, h, M_ROWS, DIM, DIM, 1);
        ln_kernel<<<M_ROWS, 256>>>(h, DIM, ln2_w + (size_t)i * DIM, ln2_b + (size_t)i * DIM, a);
        run_gemm(a, fc1_w + (size_t)i * DIM * HIDDEN, fc1_b + (size_t)i * HIDDEN,
                 nullptr, hid, M_ROWS, HIDDEN, DIM, 2);
        run_gemm(hid, fc2_w + (size_t)i * HIDDEN * DIM, fc2_b + (size_t)i * DIM,
                 h, h, M_ROWS, DIM, HIDDEN, 1);
    }

    ln_kernel<<<BATCH, 256>>>(h, (size_t)NTOK * DIM, norm_w, norm_b, cls);
    head_kernel<<<BATCH, 256>>>(cls, head_w, head_b, (float*)d_out);
}